// round 10
// baseline (speedup 1.0000x reference)
#include <cuda_runtime.h>
#include <cstdint>

// Dims: Nt=64, Nr=64, Mt=32, Mr=32, G^2=4096, num_sc=32, B=64, R=8, N_r_RF=4
#define G2 4096
typedef unsigned long long u64;

// ---- device globals (no allocation allowed) ----
// Dual-form tables (scaled 1/8):
//   g_W4[d*32+m] = (w.x, w.x, w.y, -w.y)   conj form:  acc += wxx*k + wyn*swap(k)
//   g_F4[c*32+a] = (f.x, f.x, -f.y, f.y)   mul  form
__device__ float4 g_W4[2048];
__device__ float4 g_F4[2048];
__device__ float2 g_S [(size_t)2048 * 4096];        // S[c*32+bp][g], 64 MB
__device__ float2 g_G1[(size_t)2048 * 2048];        // G1[b*32+m][c*32+s], 32 MB

// ---- f32x2 packed helpers ----
__device__ __forceinline__ u64 ffma2(u64 a, u64 b, u64 c) {
    u64 d; asm("fma.rn.f32x2 %0,%1,%2,%3;" : "=l"(d) : "l"(a), "l"(b), "l"(c)); return d;
}
__device__ __forceinline__ u64 fadd2(u64 a, u64 b) {
    u64 d; asm("add.rn.f32x2 %0,%1,%2;" : "=l"(d) : "l"(a), "l"(b)); return d;
}
__device__ __forceinline__ u64 swap2(u64 v) {
    uint2 t; asm("mov.b64 {%0,%1},%2;" : "=r"(t.x), "=r"(t.y) : "l"(v));
    u64 r;  asm("mov.b64 %0,{%1,%2};" : "=l"(r) : "r"(t.y), "r"(t.x));
    return r;
}
__device__ __forceinline__ uint32_t saddr(const void* p) {
    return (uint32_t)__cvta_generic_to_shared(p);
}
__device__ __forceinline__ void lds_v2(u64& a, u64& b, uint32_t addr) {
    asm volatile("ld.shared.v2.b64 {%0,%1},[%2];" : "=l"(a), "=l"(b) : "r"(addr));
}
__device__ __forceinline__ void ldg_v2(u64& a, u64& b, const void* p) {
    asm("ld.global.nc.v2.b64 {%0,%1},[%2];" : "=l"(a), "=l"(b) : "l"(p));
}
__device__ __forceinline__ void ldg_v2_c(u64& a, u64& b, const void* p) {
    asm volatile("ld.global.v2.b64 {%0,%1},[%2];" : "=l"(a), "=l"(b) : "l"(p));
}
__device__ __forceinline__ void stg_v2(void* p, u64 a, u64 b) {
    asm volatile("st.global.v2.b64 [%0],{%1,%2};" :: "l"(p), "l"(a), "l"(b));
}
__device__ __forceinline__ void ldg4(u64* k, const float2* p) {
    ldg_v2(k[0], k[1], p);
    ldg_v2(k[2], k[3], p + 2);
}

// ---- setup ----
__global__ void setup_kernel(const float* __restrict__ kW, const float* __restrict__ kF) {
    int i = blockIdx.x * blockDim.x + threadIdx.x;
    if (i < 2048) {
        float s, c;
        sincosf(kW[i], &s, &c);
        c *= 0.125f; s *= 0.125f;
        g_W4[i] = make_float4(c, c, s, -s);     // conj form
        sincosf(kF[i], &s, &c);
        c *= 0.125f; s *= 0.125f;
        g_F4[i] = make_float4(c, c, -s, s);     // mul form
    }
}

// =====================================================================
// Dual-batch core: 8 rows x 2 cols x 2 batch slices sharing coefficients.
// Per dd: 8 LDS.v2(bcast) + 2 LDG.v2 + 4 swaps + 64 FFMA2.
// acc = 32 u64; streams depth-2 for both slices.
// =====================================================================
#define CORE_DUAL(PTR0, PTR1, STRIDE, TADDR)                                 \
    u64 a00[8], a01[8], a10[8], a11[8];                                      \
    _Pragma("unroll")                                                        \
    for (int i = 0; i < 8; ++i) { a00[i]=0ull; a01[i]=0ull; a10[i]=0ull; a11[i]=0ull; } \
    u64 p0a,p0b,p1a,p1b, q0a,q0b,q1a,q1b;                                    \
    ldg_v2(p0a,p0b, PTR0);  ldg_v2(p1a,p1b, PTR1);                           \
    ldg_v2(q0a,q0b, (PTR0)+(STRIDE)); ldg_v2(q1a,q1b, (PTR1)+(STRIDE));      \
    _Pragma("unroll 2")                                                      \
    for (int dd = 0; dd < 64; ++dd) {                                        \
        u64 n0a=0ull,n0b=0ull,n1a=0ull,n1b=0ull;                             \
        if (dd+2 < 64) {                                                     \
            ldg_v2(n0a,n0b,(PTR0)+(size_t)(dd+2)*(STRIDE));                  \
            ldg_v2(n1a,n1b,(PTR1)+(size_t)(dd+2)*(STRIDE));                  \
        }                                                                    \
        const u64 s0a=swap2(p0a), s0b=swap2(p0b);                            \
        const u64 s1a=swap2(p1a), s1b=swap2(p1b);                            \
        _Pragma("unroll")                                                    \
        for (int i = 0; i < 8; ++i) {                                        \
            u64 wxx, wyn;                                                    \
            lds_v2(wxx, wyn, (TADDR) + (uint32_t)dd*512 + i*16);             \
            a00[i] = ffma2(wyn, s0a, ffma2(wxx, p0a, a00[i]));               \
            a01[i] = ffma2(wyn, s0b, ffma2(wxx, p0b, a01[i]));               \
            a10[i] = ffma2(wyn, s1a, ffma2(wxx, p1a, a10[i]));               \
            a11[i] = ffma2(wyn, s1b, ffma2(wxx, p1b, a11[i]));               \
        }                                                                    \
        p0a=q0a; p0b=q0b; p1a=q1a; p1b=q1b;                                  \
        q0a=n0a; q0b=n0b; q1a=n1a; q1b=n1b;                                  \
    }

#define LOAD_TABLE(DST, SRC)                                                 \
    _Pragma("unroll")                                                        \
    for (int i = 0; i < 8; ++i) DST[threadIdx.x + 256 * i] = SRC[threadIdx.x + 256 * i]; \
    __syncthreads();

// =====================================================================
// k1, grid 2048, striped: bid%4==3 -> y2n (512); else oid = bid-(bid+1)/4:
//   oid in [0,1024):  sA dual-c:  c0 = oid>>5, c1 = c0+32; gt = oid&31
//       S[c*32+bp][g] = sum_d conj(W[d,bp]) * K[c*64+d][g]
//   oid in [1024,1536): y1 dual-b: b0 = yid>>4, b1 = b0+32; cst = yid&15
//       G1[b*32+m][cs] = sum_d conj(W[d,m]) * H[b][d][cs]
// y2n WRITES Y (init).
// =====================================================================
__global__ void __launch_bounds__(256) k1_kernel(const float2* __restrict__ K,
                                                 const float2* __restrict__ H,
                                                 const float2* __restrict__ noise,
                                                 float2* __restrict__ Y) {
    __shared__ float4 Tab[2048];
    const int t = threadIdx.x;
    const unsigned bid = blockIdx.x;

    if ((bid & 3u) == 3u) {
        // ---------------- y2n ----------------
        const int blk = bid >> 2;                 // 0..511
        const int b = blk >> 3, r = blk & 7;
        Tab[t] = g_W4[(t >> 2) * 32 + r * 4 + (t & 3)];   // Wn[n*4+j]
        __syncthreads();

        const int x0 = t * 4;
        const uint32_t wn = saddr(Tab);
        const float2* np = noise + (size_t)(b * 8 + r) * 65536 + x0;

        u64 acc[4][4];
#pragma unroll
        for (int j = 0; j < 4; ++j)
#pragma unroll
            for (int q = 0; q < 4; ++q) acc[j][q] = 0ull;

#pragma unroll 4
        for (int n = 0; n < 64; ++n) {
            u64 v[4];
            ldg4(v, np + (size_t)n * 1024);
            const u64 w0 = swap2(v[0]), w1 = swap2(v[1]),
                      w2 = swap2(v[2]), w3 = swap2(v[3]);
#pragma unroll
            for (int j = 0; j < 4; ++j) {
                u64 wxx, wyn;
                lds_v2(wxx, wyn, wn + (uint32_t)((n * 4 + j) << 4));
                acc[j][0] = ffma2(wyn, w0, ffma2(wxx, v[0], acc[j][0]));
                acc[j][1] = ffma2(wyn, w1, ffma2(wxx, v[1], acc[j][1]));
                acc[j][2] = ffma2(wyn, w2, ffma2(wxx, v[2], acc[j][2]));
                acc[j][3] = ffma2(wyn, w3, ffma2(wxx, v[3], acc[j][3]));
            }
        }

        const int a = x0 >> 5, s = x0 & 31;
#pragma unroll
        for (int j = 0; j < 4; ++j) {
            float2* yp = Y + (size_t)(b * 1024 + a * 32 + r * 4 + j) * 32 + s;
            stg_v2(yp,     acc[j][0], acc[j][1]);     // WRITE (init)
            stg_v2(yp + 2, acc[j][2], acc[j][3]);
        }
        return;
    }

    LOAD_TABLE(Tab, g_W4)
    const int oid = (int)bid - (int)((bid + 1) >> 2);  // 0..1535
    const int gp = t & 63, rg = t >> 6;
    const uint32_t taddr = saddr(Tab) + (uint32_t)(rg * 8) * 16;

    if (oid < 1024) {
        // ---------------- sA (dual c) ----------------
        const int cp = oid >> 5, gt = oid & 31;
        const int g = gt * 128 + gp * 2;
        const float2* Kp0 = K + (size_t)(cp * 64) * G2 + g;
        const float2* Kp1 = Kp0 + (size_t)32 * 64 * G2;

        CORE_DUAL(Kp0, Kp1, G2, taddr)

#pragma unroll
        for (int i = 0; i < 8; ++i) {
            float2* Sp0 = g_S + (size_t)(cp * 32 + rg * 8 + i) * G2 + g;
            stg_v2(Sp0, a00[i], a01[i]);
            float2* Sp1 = g_S + (size_t)((cp + 32) * 32 + rg * 8 + i) * G2 + g;
            stg_v2(Sp1, a10[i], a11[i]);
        }
    } else {
        // ---------------- y1 (dual b) ----------------
        const int yid = oid - 1024;
        const int bb = yid >> 4, cst = yid & 15;
        const int cs = cst * 128 + gp * 2;
        const float2* Hp0 = H + (size_t)bb * 131072 + cs;       // + d*2048
        const float2* Hp1 = Hp0 + (size_t)32 * 131072;

        CORE_DUAL(Hp0, Hp1, 2048, taddr)

#pragma unroll
        for (int i = 0; i < 8; ++i) {
            float2* Gp0 = g_G1 + (size_t)(bb * 32 + rg * 8 + i) * 2048 + cs;
            stg_v2(Gp0, a00[i], a01[i]);
            float2* Gp1 = g_G1 + (size_t)((bb + 32) * 32 + rg * 8 + i) * 2048 + cs;
            stg_v2(Gp1, a10[i], a11[i]);
        }
    }
}

// =====================================================================
// k2, grid 768, striped: bid%3==2 -> y2s (256, dual bm, RMW);
// else pid = bid-(bid+1)/3 in [0,512):
//   phiB dual-bp: bp0 = pid>>5, bp1 = bp0+16; gt = pid&31
//     Phi[(a*32+bp)][g] = sum_c F[c,a] * S[c*32+bp][g]
//   y2s: Y[b][(a*32+m)][s] += sum_c F[c,a] * G1[b*32+m][c*32+s]
// =====================================================================
__global__ void __launch_bounds__(256) k2_kernel(float2* __restrict__ Phi,
                                                 float2* __restrict__ Y) {
    __shared__ float4 Ft[2048];
    const int t = threadIdx.x;
    const unsigned bid = blockIdx.x;
    LOAD_TABLE(Ft, g_F4)

    if (bid % 3u == 2u) {
        // ---------------- y2s (dual bm, RMW) ----------------
        const int sid = bid / 3u;                 // 0..255
        const int sub = t >> 6;                   // 0..3
        const int bm0 = sid * 8 + sub * 2;        // even bm
        const int bm1 = bm0 + 1;
        const int b = bm0 >> 5, m0 = bm0 & 31, m1 = bm1 & 31;
        const int tsub = t & 63;
        const int sp = tsub & 15, ag = tsub >> 4;
        const int s = sp * 2;

        const float2* Gp0 = g_G1 + (size_t)bm0 * 2048 + s;   // + c*32
        const float2* Gp1 = g_G1 + (size_t)bm1 * 2048 + s;
        const uint32_t faddr = saddr(Ft) + (uint32_t)(ag * 8) * 16;

        CORE_DUAL(Gp0, Gp1, 32, faddr)

#pragma unroll
        for (int i = 0; i < 8; ++i) {
            const int a = ag * 8 + i;
            float2* yp0 = Y + (size_t)(b * 1024 + a * 32 + m0) * 32 + s;
            u64 y0, y1;
            ldg_v2_c(y0, y1, yp0);
            stg_v2(yp0, fadd2(y0, a00[i]), fadd2(y1, a01[i]));
            float2* yp1 = Y + (size_t)(b * 1024 + a * 32 + m1) * 32 + s;
            ldg_v2_c(y0, y1, yp1);
            stg_v2(yp1, fadd2(y0, a10[i]), fadd2(y1, a11[i]));
        }
    } else {
        // ---------------- phiB (dual bp) ----------------
        const int pid = (int)bid - (int)((bid + 1) / 3u);    // 0..511
        const int gp = t & 63, rg = t >> 6;
        const int pp = pid >> 5, gt = pid & 31;
        const int g = gt * 128 + gp * 2;

        const float2* Sp0 = g_S + (size_t)pp * G2 + g;       // + c*32*G2
        const float2* Sp1 = Sp0 + (size_t)16 * G2;
        const uint32_t faddr = saddr(Ft) + (uint32_t)(rg * 8) * 16;

        CORE_DUAL(Sp0, Sp1, (size_t)32 * G2, faddr)

#pragma unroll
        for (int i = 0; i < 8; ++i) {
            const int a = rg * 8 + i;
            float2* Pp0 = Phi + (size_t)(a * 32 + pp) * G2 + g;
            stg_v2(Pp0, a00[i], a01[i]);
            float2* Pp1 = Phi + (size_t)(a * 32 + pp + 16) * G2 + g;
            stg_v2(Pp1, a10[i], a11[i]);
        }
    }
}

extern "C" void kernel_launch(void* const* d_in, const int* in_sizes, int n_in,
                              void* d_out, int out_size) {
    const float2* H     = (const float2*)d_in[0];  // (64,64,64,32,2) f32
    const float2* noise = (const float2*)d_in[1];  // (64,8,64,1024,2) f32
    const float*  kW    = (const float*)d_in[2];   // (64,32)
    const float*  kF    = (const float*)d_in[3];   // (64,32)
    const float2* K     = (const float2*)d_in[4];  // (4096,4096,2)

    float2* Phi = (float2*)d_out;                   // 1024*4096 complex
    float2* Y   = Phi + (size_t)1024 * 4096;        // 64*1024*32 complex

    setup_kernel<<<8, 256>>>(kW, kF);
    k1_kernel<<<2048, 256>>>(K, H, noise, Y);
    k2_kernel<<<768, 256>>>(Phi, Y);
}

// round 11
// speedup vs baseline: 1.2723x; 1.2723x over previous
#include <cuda_runtime.h>
#include <cstdint>

// Dims: Nt=64, Nr=64, Mt=32, Mr=32, G^2=4096, num_sc=32, B=64, R=8, N_r_RF=4
#define G2 4096
typedef unsigned long long u64;

// ---- device globals (no allocation allowed) ----
// Dual-form tables (scaled 1/8):
//   g_W4[d*32+m] = (w.x, w.x, w.y, -w.y)   conj form:  acc += wxx*k + wyn*swap(k)
//   g_F4[c*32+a] = (f.x, f.x, -f.y, f.y)   mul  form
__device__ float4 g_W4[2048];
__device__ float4 g_F4[2048];
__device__ float2 g_S [(size_t)2048 * 4096];        // S[c*32+bp][g], 64 MB
__device__ float2 g_G1[(size_t)2048 * 2048];        // G1[b*32+m][c*32+s], 32 MB

// ---- f32x2 packed helpers ----
__device__ __forceinline__ u64 ffma2(u64 a, u64 b, u64 c) {
    u64 d; asm("fma.rn.f32x2 %0,%1,%2,%3;" : "=l"(d) : "l"(a), "l"(b), "l"(c)); return d;
}
__device__ __forceinline__ u64 fadd2(u64 a, u64 b) {
    u64 d; asm("add.rn.f32x2 %0,%1,%2;" : "=l"(d) : "l"(a), "l"(b)); return d;
}
__device__ __forceinline__ u64 swap2(u64 v) {
    uint2 t; asm("mov.b64 {%0,%1},%2;" : "=r"(t.x), "=r"(t.y) : "l"(v));
    u64 r;  asm("mov.b64 %0,{%1,%2};" : "=l"(r) : "r"(t.y), "r"(t.x));
    return r;
}
__device__ __forceinline__ uint32_t saddr(const void* p) {
    return (uint32_t)__cvta_generic_to_shared(p);
}
__device__ __forceinline__ void lds_v2(u64& a, u64& b, uint32_t addr) {
    asm volatile("ld.shared.v2.b64 {%0,%1},[%2];" : "=l"(a), "=l"(b) : "r"(addr));
}
__device__ __forceinline__ void ldg_v2(u64& a, u64& b, const void* p) {
    asm("ld.global.nc.v2.b64 {%0,%1},[%2];" : "=l"(a), "=l"(b) : "l"(p));
}
__device__ __forceinline__ void ldg_v2_c(u64& a, u64& b, const void* p) {
    asm volatile("ld.global.v2.b64 {%0,%1},[%2];" : "=l"(a), "=l"(b) : "l"(p));
}
__device__ __forceinline__ void stg_v2(void* p, u64 a, u64 b) {
    asm volatile("st.global.v2.b64 [%0],{%1,%2};" :: "l"(p), "l"(a), "l"(b));
}
__device__ __forceinline__ void ldg4(u64* k, const float2* p) {
    ldg_v2(k[0], k[1], p);
    ldg_v2(k[2], k[3], p + 2);
}
__device__ __forceinline__ void pref_l2(const void* p) {
    asm volatile("prefetch.global.L2 [%0];" :: "l"(p));
}

// ---- setup ----
__global__ void setup_kernel(const float* __restrict__ kW, const float* __restrict__ kF) {
    int i = blockIdx.x * blockDim.x + threadIdx.x;
    if (i < 2048) {
        float s, c;
        sincosf(kW[i], &s, &c);
        c *= 0.125f; s *= 0.125f;
        g_W4[i] = make_float4(c, c, s, -s);     // conj form
        sincosf(kF[i], &s, &c);
        c *= 0.125f; s *= 0.125f;
        g_F4[i] = make_float4(c, c, -s, s);     // mul form
    }
}

// =====================================================================
// R4-proven core + L2 prefetch: thread tile = 8 rows x 2 cols, K=64.
// Per dd: 8 LDS.v2(16B bcast) + 1 LDG.v2(16B) + 1 L2-prefetch(+6)
//         + 2 swaps + 32 FFMA2.  Depth-2 register prefetch, unroll 2.
// TADDR: shared table base incl. row-group offset.
// =====================================================================
#define CORE8x2(PTR, STRIDE, TADDR)                                          \
    u64 acc0[8], acc1[8];                                                    \
    _Pragma("unroll")                                                        \
    for (int i = 0; i < 8; ++i) { acc0[i] = 0ull; acc1[i] = 0ull; }          \
    u64 ka0, ka1, kb0, kb1;                                                  \
    ldg_v2(ka0, ka1, PTR);                                                   \
    ldg_v2(kb0, kb1, (PTR) + (STRIDE));                                      \
    _Pragma("unroll")                                                        \
    for (int pd = 2; pd < 6; ++pd) pref_l2((PTR) + (size_t)pd * (STRIDE));   \
    _Pragma("unroll 2")                                                      \
    for (int dd = 0; dd < 64; ++dd) {                                        \
        u64 kn0 = 0ull, kn1 = 0ull;                                          \
        if (dd + 2 < 64) ldg_v2(kn0, kn1, (PTR) + (size_t)(dd + 2) * (STRIDE)); \
        if (dd + 6 < 64) pref_l2((PTR) + (size_t)(dd + 6) * (STRIDE));       \
        const u64 ks0 = swap2(ka0), ks1 = swap2(ka1);                        \
        _Pragma("unroll")                                                    \
        for (int i = 0; i < 8; ++i) {                                        \
            u64 wxx, wyn;                                                    \
            lds_v2(wxx, wyn, (TADDR) + (uint32_t)dd * 512 + i * 16);         \
            acc0[i] = ffma2(wyn, ks0, ffma2(wxx, ka0, acc0[i]));             \
            acc1[i] = ffma2(wyn, ks1, ffma2(wxx, ka1, acc1[i]));             \
        }                                                                    \
        ka0 = kb0; ka1 = kb1; kb0 = kn0; kb1 = kn1;                          \
    }

#define LOAD_TABLE(DST, SRC)                                                 \
    _Pragma("unroll")                                                        \
    for (int i = 0; i < 8; ++i) DST[threadIdx.x + 256 * i] = SRC[threadIdx.x + 256 * i]; \
    __syncthreads();

// =====================================================================
// k1, grid 3584, striped: blockIdx%7==6 -> y2n (512 blocks, DRAM-bound),
// else other_id = blockIdx - blockIdx/7:
//   [0,2048):  sA:  S[c*32+bp][g] = sum_d conj(W[d,bp]) * K[c*64+d][g]
//   [2048,3072): y1: G1[b*32+m][cs] = sum_d conj(W[d,m]) * H[b][d][cs]
// y2n WRITES Y (init): Y[b][a*32+r*4+j][s] = sum_n conj(W[n,r4j])*noise
// =====================================================================
__global__ void __launch_bounds__(256) k1_kernel(const float2* __restrict__ K,
                                                 const float2* __restrict__ H,
                                                 const float2* __restrict__ noise,
                                                 float2* __restrict__ Y) {
    __shared__ float4 Tab[2048];
    const int t = threadIdx.x;
    const unsigned bid = blockIdx.x;

    if (bid % 7u == 6u) {
        // ---------------- y2n ----------------
        const int blk = bid / 7u;                 // 0..511
        const int b = blk >> 3, r = blk & 7;
        Tab[t] = g_W4[(t >> 2) * 32 + r * 4 + (t & 3)];   // Wn[n*4+j]
        __syncthreads();

        const int x0 = t * 4;
        const uint32_t wn = saddr(Tab);
        const float2* np = noise + (size_t)(b * 8 + r) * 65536 + x0;

        u64 acc[4][4];
#pragma unroll
        for (int j = 0; j < 4; ++j)
#pragma unroll
            for (int q = 0; q < 4; ++q) acc[j][q] = 0ull;

#pragma unroll 4
        for (int n = 0; n < 64; ++n) {
            u64 v[4];
            ldg4(v, np + (size_t)n * 1024);
            if (n + 8 < 64) pref_l2(np + (size_t)(n + 8) * 1024);
            const u64 w0 = swap2(v[0]), w1 = swap2(v[1]),
                      w2 = swap2(v[2]), w3 = swap2(v[3]);
#pragma unroll
            for (int j = 0; j < 4; ++j) {
                u64 wxx, wyn;
                lds_v2(wxx, wyn, wn + (uint32_t)((n * 4 + j) << 4));
                acc[j][0] = ffma2(wyn, w0, ffma2(wxx, v[0], acc[j][0]));
                acc[j][1] = ffma2(wyn, w1, ffma2(wxx, v[1], acc[j][1]));
                acc[j][2] = ffma2(wyn, w2, ffma2(wxx, v[2], acc[j][2]));
                acc[j][3] = ffma2(wyn, w3, ffma2(wxx, v[3], acc[j][3]));
            }
        }

        const int a = x0 >> 5, s = x0 & 31;
#pragma unroll
        for (int j = 0; j < 4; ++j) {
            float2* yp = Y + (size_t)(b * 1024 + a * 32 + r * 4 + j) * 32 + s;
            stg_v2(yp,     acc[j][0], acc[j][1]);     // WRITE (init)
            stg_v2(yp + 2, acc[j][2], acc[j][3]);
        }
        return;
    }

    // non-y2n blocks: shared W table
    LOAD_TABLE(Tab, g_W4)
    const int oid = bid - bid / 7u;               // 0..3071
    const int gp = t & 63, rg = t >> 6;
    const uint32_t taddr = saddr(Tab) + (uint32_t)(rg * 8) * 16;

    if (oid < 2048) {
        // ---------------- sA ----------------
        const int c = oid >> 5, gt = oid & 31;
        const int g = gt * 128 + gp * 2;
        const float2* Kp = K + (size_t)(c * 64) * G2 + g;

        CORE8x2(Kp, G2, taddr)

#pragma unroll
        for (int i = 0; i < 8; ++i) {
            float2* Sp = g_S + (size_t)(c * 32 + rg * 8 + i) * G2 + g;
            stg_v2(Sp, acc0[i], acc1[i]);
        }
    } else {
        // ---------------- y1 ----------------
        const int blk = oid - 2048;
        const int b = blk >> 4, cst = blk & 15;
        const int cs = cst * 128 + gp * 2;
        const float2* Hp = H + (size_t)b * 131072 + cs;    // + d*2048

        CORE8x2(Hp, 2048, taddr)

#pragma unroll
        for (int i = 0; i < 8; ++i) {
            float2* Gp = g_G1 + (size_t)(b * 32 + rg * 8 + i) * 2048 + cs;
            stg_v2(Gp, acc0[i], acc1[i]);
        }
    }
}

// =====================================================================
// k2, grid 1536, striped: blockIdx%3==2 -> y2s (512 blocks, RMW),
// else phi_id = blockIdx - blockIdx/3 in [0,1024):
//   phiB: Phi[(a*32+bp)][g] = sum_c F[c,a] * S[c*32+bp][g]
//   y2s:  Y[b][(a*32+m)][s] += sum_c F[c,a] * G1[b*32+m][c*32+s]
// =====================================================================
__global__ void __launch_bounds__(256) k2_kernel(float2* __restrict__ Phi,
                                                 float2* __restrict__ Y) {
    __shared__ float4 Ft[2048];
    const int t = threadIdx.x;
    const unsigned bid = blockIdx.x;
    LOAD_TABLE(Ft, g_F4)

    if (bid % 3u == 2u) {
        // ---------------- y2s (RMW) ----------------
        const int blk = bid / 3u;                 // 0..511
        const int bm = blk * 4 + (t >> 6);
        const int b = bm >> 5, m = bm & 31;
        const int sp = t & 15, ag = (t >> 4) & 3;
        const int s = sp * 2;

        const float2* Gp = g_G1 + (size_t)bm * 2048 + s;   // + c*32
        const uint32_t faddr = saddr(Ft) + (uint32_t)(ag * 8) * 16;

        CORE8x2(Gp, 32, faddr)

#pragma unroll
        for (int i = 0; i < 8; ++i) {
            float2* yp = Y + (size_t)(b * 1024 + (ag * 8 + i) * 32 + m) * 32 + s;
            u64 y0, y1;
            ldg_v2_c(y0, y1, yp);
            stg_v2(yp, fadd2(y0, acc0[i]), fadd2(y1, acc1[i]));
        }
    } else {
        // ---------------- phiB ----------------
        const int pid = bid - bid / 3u;           // 0..1023
        const int gp = t & 63, ag = t >> 6;
        const int bp = pid >> 5, gt = pid & 31;
        const int g = gt * 128 + gp * 2;

        const float2* Sp = g_S + (size_t)bp * G2 + g;      // + c*32*G2
        const uint32_t faddr = saddr(Ft) + (uint32_t)(ag * 8) * 16;

        CORE8x2(Sp, (size_t)32 * G2, faddr)

#pragma unroll
        for (int i = 0; i < 8; ++i) {
            float2* Pp = Phi + (size_t)((ag * 8 + i) * 32 + bp) * G2 + g;
            stg_v2(Pp, acc0[i], acc1[i]);
        }
    }
}

extern "C" void kernel_launch(void* const* d_in, const int* in_sizes, int n_in,
                              void* d_out, int out_size) {
    const float2* H     = (const float2*)d_in[0];  // (64,64,64,32,2) f32
    const float2* noise = (const float2*)d_in[1];  // (64,8,64,1024,2) f32
    const float*  kW    = (const float*)d_in[2];   // (64,32)
    const float*  kF    = (const float*)d_in[3];   // (64,32)
    const float2* K     = (const float2*)d_in[4];  // (4096,4096,2)

    float2* Phi = (float2*)d_out;                   // 1024*4096 complex
    float2* Y   = Phi + (size_t)1024 * 4096;        // 64*1024*32 complex

    setup_kernel<<<8, 256>>>(kW, kF);
    k1_kernel<<<3584, 256>>>(K, H, noise, Y);
    k2_kernel<<<1536, 256>>>(Phi, Y);
}

// round 12
// speedup vs baseline: 1.4635x; 1.1503x over previous
#include <cuda_runtime.h>
#include <cstdint>

// Dims: Nt=64, Nr=64, Mt=32, Mr=32, G^2=4096, num_sc=32, B=64, R=8, N_r_RF=4
#define G2 4096
typedef unsigned long long u64;

// ---- device globals (no allocation allowed) ----
// Dual-form tables (scaled 1/8):
//   g_W4[d*32+m] = (w.x, w.x, w.y, -w.y)   conj form:  acc += wxx*k + wyn*swap(k)
//   g_F4[c*32+a] = (f.x, f.x, -f.y, f.y)   mul  form
__device__ float4 g_W4[2048];
__device__ float4 g_F4[2048];
__device__ float2 g_S [(size_t)2048 * 4096];        // S[c*32+bp][g], 64 MB
__device__ float2 g_G1[(size_t)2048 * 2048];        // G1[b*32+m][c*32+s], 32 MB

// ---- f32x2 packed helpers ----
__device__ __forceinline__ u64 ffma2(u64 a, u64 b, u64 c) {
    u64 d; asm("fma.rn.f32x2 %0,%1,%2,%3;" : "=l"(d) : "l"(a), "l"(b), "l"(c)); return d;
}
__device__ __forceinline__ u64 fadd2(u64 a, u64 b) {
    u64 d; asm("add.rn.f32x2 %0,%1,%2;" : "=l"(d) : "l"(a), "l"(b)); return d;
}
__device__ __forceinline__ u64 swap2(u64 v) {
    uint2 t; asm("mov.b64 {%0,%1},%2;" : "=r"(t.x), "=r"(t.y) : "l"(v));
    u64 r;  asm("mov.b64 %0,{%1,%2};" : "=l"(r) : "r"(t.y), "r"(t.x));
    return r;
}
__device__ __forceinline__ uint32_t saddr(const void* p) {
    return (uint32_t)__cvta_generic_to_shared(p);
}
__device__ __forceinline__ void lds_v2(u64& a, u64& b, uint32_t addr) {
    asm volatile("ld.shared.v2.b64 {%0,%1},[%2];" : "=l"(a), "=l"(b) : "r"(addr));
}
__device__ __forceinline__ void ldg_v2(u64& a, u64& b, const void* p) {
    asm("ld.global.nc.v2.b64 {%0,%1},[%2];" : "=l"(a), "=l"(b) : "l"(p));
}
__device__ __forceinline__ void ldg_v2_c(u64& a, u64& b, const void* p) {
    asm volatile("ld.global.v2.b64 {%0,%1},[%2];" : "=l"(a), "=l"(b) : "l"(p));
}
__device__ __forceinline__ void stg_v2(void* p, u64 a, u64 b) {
    asm volatile("st.global.v2.b64 [%0],{%1,%2};" :: "l"(p), "l"(a), "l"(b));
}
__device__ __forceinline__ void ldg4(u64* k, const float2* p) {
    ldg_v2(k[0], k[1], p);
    ldg_v2(k[2], k[3], p + 2);
}
__device__ __forceinline__ void pref_l2(const void* p) {
    asm volatile("prefetch.global.L2 [%0];" :: "l"(p));
}

// ---- setup ----
__global__ void setup_kernel(const float* __restrict__ kW, const float* __restrict__ kF) {
    int i = blockIdx.x * blockDim.x + threadIdx.x;
    if (i < 2048) {
        float s, c;
        sincosf(kW[i], &s, &c);
        c *= 0.125f; s *= 0.125f;
        g_W4[i] = make_float4(c, c, s, -s);     // conj form
        sincosf(kF[i], &s, &c);
        c *= 0.125f; s *= 0.125f;
        g_F4[i] = make_float4(c, c, -s, s);     // mul form
    }
}

// =====================================================================
// R4-proven core + L2 prefetch + guard peeling.
// Thread tile = 8 rows x 2 cols, K=64. Per dd (hot phase):
//   8 LDS.v2(bcast) + 1 LDG.v2 + 1 L2-pref + 2 swaps + 32 FFMA2,
//   NO predicates, NO dead zero-init.
// =====================================================================
#define C8X2_BODY(DD)                                                        \
    {                                                                        \
        const u64 ks0 = swap2(ka0), ks1 = swap2(ka1);                        \
        _Pragma("unroll")                                                    \
        for (int i = 0; i < 8; ++i) {                                        \
            u64 wxx, wyn;                                                    \
            lds_v2(wxx, wyn, taddr_ + (uint32_t)(DD) * 512 + i * 16);        \
            acc0[i] = ffma2(wyn, ks0, ffma2(wxx, ka0, acc0[i]));             \
            acc1[i] = ffma2(wyn, ks1, ffma2(wxx, ka1, acc1[i]));             \
        }                                                                    \
        ka0 = kb0; ka1 = kb1; kb0 = kn0; kb1 = kn1;                          \
    }

#define CORE8x2(PTR, STRIDE, TADDR)                                          \
    u64 acc0[8], acc1[8];                                                    \
    _Pragma("unroll")                                                        \
    for (int i = 0; i < 8; ++i) { acc0[i] = 0ull; acc1[i] = 0ull; }          \
    const uint32_t taddr_ = (TADDR);                                         \
    u64 ka0, ka1, kb0, kb1;                                                  \
    ldg_v2(ka0, ka1, (PTR));                                                 \
    ldg_v2(kb0, kb1, (PTR) + (STRIDE));                                      \
    _Pragma("unroll")                                                        \
    for (int pd = 2; pd < 6; ++pd) pref_l2((PTR) + (size_t)pd * (STRIDE));   \
    _Pragma("unroll 2")                                                      \
    for (int dd = 0; dd < 56; ++dd) {                                        \
        u64 kn0, kn1;                                                        \
        ldg_v2(kn0, kn1, (PTR) + (size_t)(dd + 2) * (STRIDE));               \
        pref_l2((PTR) + (size_t)(dd + 6) * (STRIDE));                        \
        C8X2_BODY(dd)                                                        \
    }                                                                        \
    _Pragma("unroll 2")                                                      \
    for (int dd = 56; dd < 62; ++dd) {                                       \
        u64 kn0, kn1;                                                        \
        ldg_v2(kn0, kn1, (PTR) + (size_t)(dd + 2) * (STRIDE));               \
        C8X2_BODY(dd)                                                        \
    }                                                                        \
    _Pragma("unroll")                                                        \
    for (int dd = 62; dd < 64; ++dd) {                                       \
        u64 kn0 = 0ull, kn1 = 0ull;                                          \
        C8X2_BODY(dd)                                                        \
    }

#define LOAD_TABLE(DST, SRC)                                                 \
    _Pragma("unroll")                                                        \
    for (int i = 0; i < 8; ++i) DST[threadIdx.x + 256 * i] = SRC[threadIdx.x + 256 * i]; \
    __syncthreads();

// =====================================================================
// k1, grid 3584, striped: blockIdx%7==6 -> y2n (512 blocks, DRAM-bound),
// else other_id = blockIdx - blockIdx/7:
//   [0,2048):  sA:  S[c*32+bp][g] = sum_d conj(W[d,bp]) * K[c*64+d][g]
//   [2048,3072): y1: G1[b*32+m][cs] = sum_d conj(W[d,m]) * H[b][d][cs]
// y2n WRITES Y (init): Y[b][a*32+r*4+j][s] = sum_n conj(W[n,r4j])*noise
// =====================================================================
__global__ void __launch_bounds__(256, 3) k1_kernel(const float2* __restrict__ K,
                                                    const float2* __restrict__ H,
                                                    const float2* __restrict__ noise,
                                                    float2* __restrict__ Y) {
    __shared__ float4 Tab[2048];
    const int t = threadIdx.x;
    const unsigned bid = blockIdx.x;

    if (bid % 7u == 6u) {
        // ---------------- y2n ----------------
        const int blk = bid / 7u;                 // 0..511
        const int b = blk >> 3, r = blk & 7;
        Tab[t] = g_W4[(t >> 2) * 32 + r * 4 + (t & 3)];   // Wn[n*4+j]
        __syncthreads();

        const int x0 = t * 4;
        const uint32_t wn = saddr(Tab);
        const float2* np = noise + (size_t)(b * 8 + r) * 65536 + x0;

        u64 acc[4][4];
#pragma unroll
        for (int j = 0; j < 4; ++j)
#pragma unroll
            for (int q = 0; q < 4; ++q) acc[j][q] = 0ull;

#define Y2N_BODY(N)                                                          \
        {                                                                    \
            const u64 w0 = swap2(v[0]), w1 = swap2(v[1]),                    \
                      w2 = swap2(v[2]), w3 = swap2(v[3]);                    \
            _Pragma("unroll")                                                \
            for (int j = 0; j < 4; ++j) {                                    \
                u64 wxx, wyn;                                                \
                lds_v2(wxx, wyn, wn + (uint32_t)(((N) * 4 + j) << 4));       \
                acc[j][0] = ffma2(wyn, w0, ffma2(wxx, v[0], acc[j][0]));     \
                acc[j][1] = ffma2(wyn, w1, ffma2(wxx, v[1], acc[j][1]));     \
                acc[j][2] = ffma2(wyn, w2, ffma2(wxx, v[2], acc[j][2]));     \
                acc[j][3] = ffma2(wyn, w3, ffma2(wxx, v[3], acc[j][3]));     \
            }                                                                \
        }

#pragma unroll 4
        for (int n = 0; n < 56; ++n) {
            u64 v[4];
            ldg4(v, np + (size_t)n * 1024);
            pref_l2(np + (size_t)(n + 8) * 1024);
            Y2N_BODY(n)
        }
#pragma unroll 4
        for (int n = 56; n < 64; ++n) {
            u64 v[4];
            ldg4(v, np + (size_t)n * 1024);
            Y2N_BODY(n)
        }

        const int a = x0 >> 5, s = x0 & 31;
#pragma unroll
        for (int j = 0; j < 4; ++j) {
            float2* yp = Y + (size_t)(b * 1024 + a * 32 + r * 4 + j) * 32 + s;
            stg_v2(yp,     acc[j][0], acc[j][1]);     // WRITE (init)
            stg_v2(yp + 2, acc[j][2], acc[j][3]);
        }
        return;
    }

    // non-y2n blocks: shared W table
    LOAD_TABLE(Tab, g_W4)
    const int oid = bid - bid / 7u;               // 0..3071
    const int gp = t & 63, rg = t >> 6;
    const uint32_t taddr = saddr(Tab) + (uint32_t)(rg * 8) * 16;

    if (oid < 2048) {
        // ---------------- sA ----------------
        const int c = oid >> 5, gt = oid & 31;
        const int g = gt * 128 + gp * 2;
        const float2* Kp = K + (size_t)(c * 64) * G2 + g;

        CORE8x2(Kp, G2, taddr)

#pragma unroll
        for (int i = 0; i < 8; ++i) {
            float2* Sp = g_S + (size_t)(c * 32 + rg * 8 + i) * G2 + g;
            stg_v2(Sp, acc0[i], acc1[i]);
        }
    } else {
        // ---------------- y1 ----------------
        const int blk = oid - 2048;
        const int b = blk >> 4, cst = blk & 15;
        const int cs = cst * 128 + gp * 2;
        const float2* Hp = H + (size_t)b * 131072 + cs;    // + d*2048

        CORE8x2(Hp, 2048, taddr)

#pragma unroll
        for (int i = 0; i < 8; ++i) {
            float2* Gp = g_G1 + (size_t)(b * 32 + rg * 8 + i) * 2048 + cs;
            stg_v2(Gp, acc0[i], acc1[i]);
        }
    }
}

// =====================================================================
// k2, grid 1536, striped: blockIdx%3==2 -> y2s (512 blocks, RMW),
// else phi_id = blockIdx - blockIdx/3 in [0,1024):
//   phiB: Phi[(a*32+bp)][g] = sum_c F[c,a] * S[c*32+bp][g]
//   y2s:  Y[b][(a*32+m)][s] += sum_c F[c,a] * G1[b*32+m][c*32+s]
// =====================================================================
__global__ void __launch_bounds__(256, 3) k2_kernel(float2* __restrict__ Phi,
                                                    float2* __restrict__ Y) {
    __shared__ float4 Ft[2048];
    const int t = threadIdx.x;
    const unsigned bid = blockIdx.x;
    LOAD_TABLE(Ft, g_F4)

    if (bid % 3u == 2u) {
        // ---------------- y2s (RMW) ----------------
        const int blk = bid / 3u;                 // 0..511
        const int bm = blk * 4 + (t >> 6);
        const int b = bm >> 5, m = bm & 31;
        const int sp = t & 15, ag = (t >> 4) & 3;
        const int s = sp * 2;

        const float2* Gp = g_G1 + (size_t)bm * 2048 + s;   // + c*32
        const uint32_t faddr = saddr(Ft) + (uint32_t)(ag * 8) * 16;

        CORE8x2(Gp, 32, faddr)

#pragma unroll
        for (int i = 0; i < 8; ++i) {
            float2* yp = Y + (size_t)(b * 1024 + (ag * 8 + i) * 32 + m) * 32 + s;
            u64 y0, y1;
            ldg_v2_c(y0, y1, yp);
            stg_v2(yp, fadd2(y0, acc0[i]), fadd2(y1, acc1[i]));
        }
    } else {
        // ---------------- phiB ----------------
        const int pid = bid - bid / 3u;           // 0..1023
        const int gp = t & 63, ag = t >> 6;
        const int bp = pid >> 5, gt = pid & 31;
        const int g = gt * 128 + gp * 2;

        const float2* Sp = g_S + (size_t)bp * G2 + g;      // + c*32*G2
        const uint32_t faddr = saddr(Ft) + (uint32_t)(ag * 8) * 16;

        CORE8x2(Sp, (size_t)32 * G2, faddr)

#pragma unroll
        for (int i = 0; i < 8; ++i) {
            float2* Pp = Phi + (size_t)((ag * 8 + i) * 32 + bp) * G2 + g;
            stg_v2(Pp, acc0[i], acc1[i]);
        }
    }
}

extern "C" void kernel_launch(void* const* d_in, const int* in_sizes, int n_in,
                              void* d_out, int out_size) {
    const float2* H     = (const float2*)d_in[0];  // (64,64,64,32,2) f32
    const float2* noise = (const float2*)d_in[1];  // (64,8,64,1024,2) f32
    const float*  kW    = (const float*)d_in[2];   // (64,32)
    const float*  kF    = (const float*)d_in[3];   // (64,32)
    const float2* K     = (const float2*)d_in[4];  // (4096,4096,2)

    float2* Phi = (float2*)d_out;                   // 1024*4096 complex
    float2* Y   = Phi + (size_t)1024 * 4096;        // 64*1024*32 complex

    setup_kernel<<<8, 256>>>(kW, kF);
    k1_kernel<<<3584, 256>>>(K, H, noise, Y);
    k2_kernel<<<1536, 256>>>(Phi, Y);
}